// round 10
// baseline (speedup 1.0000x reference)
#include <cuda_runtime.h>
#include <cuda_fp16.h>
#include <cstdint>

#define BQ 8192
#define HDIM 512
#define HK 8192
#define NT2 64               // gemm2 n-tiles = 8192/128
#define NC 8                 // k chunks of 64
#define STAGE_BYTES 32768    // A 16K + B 16K
#define DYN1 98304           // gemm1: 3 stages
#define DYN2 106496          // gemm2: 3 stages + vbuf 4K + red 4K

// ---------------- device scratch (no cudaMalloc allowed) -------------------
__device__ __align__(16) __half g_a1[BQ*HDIM];
__device__ __align__(16) __half g_h [BQ*HDIM];
__device__ __align__(16) __half g_w1[HDIM*HDIM];
__device__ __align__(16) __half g_w2[(size_t)HK*HDIM];
__device__ float g_ldp[(size_t)NT2*BQ];   // [ntile][row] - coalesced both sides

// ---------------- helpers ---------------------------------------------------
__device__ __forceinline__ uint32_t smem_u32(const void* p){
    uint32_t a;
    asm("{ .reg .u64 t; cvta.to.shared.u64 t, %1; cvt.u32.u64 %0, t; }" : "=r"(a) : "l"(p));
    return a;
}
__device__ __forceinline__ void cp16(uint32_t dst, const void* src){
    asm volatile("cp.async.cg.shared.global [%0], [%1], 16;" :: "r"(dst), "l"(src));
}
__device__ __forceinline__ void cp_commit(){
    asm volatile("cp.async.commit_group;" ::: "memory");
}
template<int N> __device__ __forceinline__ void cp_wait(){
    asm volatile("cp.async.wait_group %0;" :: "n"(N) : "memory");
}
__device__ __forceinline__ void ldsm4(uint32_t* r, uint32_t addr){
    asm volatile("ldmatrix.sync.aligned.m8n8.x4.shared.b16 {%0,%1,%2,%3}, [%4];"
        : "=r"(r[0]), "=r"(r[1]), "=r"(r[2]), "=r"(r[3]) : "r"(addr));
}
__device__ __forceinline__ void mma16816(float* d, const uint32_t* a, const uint32_t* b){
    asm volatile("mma.sync.aligned.m16n8k16.row.col.f32.f16.f16.f32 "
        "{%0,%1,%2,%3},{%4,%5,%6,%7},{%8,%9},{%0,%1,%2,%3};"
        : "+f"(d[0]), "+f"(d[1]), "+f"(d[2]), "+f"(d[3])
        : "r"(a[0]), "r"(a[1]), "r"(a[2]), "r"(a[3]), "r"(b[0]), "r"(b[1]));
}
__device__ __forceinline__ float fast_tanh(float x){
    x = fminf(fmaxf(x, -15.f), 15.f);
    float e = __expf(2.f * x);
    return __fdividef(e - 1.f, e + 1.f);
}

// ---------------- mainloop (128 threads, 4 warps, warp tile 64x64) ----------
__device__ __forceinline__ void issue_chunk(
    int c, uint32_t sbase,
    const __half* __restrict__ a, const __half* __restrict__ b,
    int row0, int n0, int tid)
{
    const int kk = c << 6;
#pragma unroll
    for (int j = 0; j < 8; ++j) {                // A: 128 rows x 128B
        int i = tid + 128 * j;
        int r = i >> 3, q = i & 7;
        uint32_t sw = (uint32_t)(r * 128) + ((uint32_t)(q ^ (r & 7)) << 4);
        cp16(sbase + sw, a + (size_t)(row0 + r) * HDIM + kk + q * 8);
    }
#pragma unroll
    for (int j = 0; j < 8; ++j) {                // B: 128 n-rows x 128B
        int i = tid + 128 * j;
        int r = i >> 3, q = i & 7;
        uint32_t sw = (uint32_t)(r * 128) + ((uint32_t)(q ^ (r & 7)) << 4);
        cp16(sbase + 16384u + sw, b + (size_t)(n0 + r) * HDIM + kk + q * 8);
    }
    cp_commit();
}

__device__ __forceinline__ void gemm_mainloop(
    const __half* a, const __half* b, int row0, int n0,
    uint32_t sb, int tid, int lane, int wm, int wn,
    float acc[4][8][4])
{
#pragma unroll
    for (int mi = 0; mi < 4; ++mi)
#pragma unroll
        for (int ni = 0; ni < 8; ++ni)
#pragma unroll
            for (int q = 0; q < 4; ++q) acc[mi][ni][q] = 0.f;

    const int arow = wm * 64 + (lane & 15);
    const int ahl  = lane >> 4;
    const int brow = wn * 64 + (lane & 7) + ((lane >> 4) << 3);
    const int bhl  = (lane >> 3) & 1;

    issue_chunk(0, sb,               a, b, row0, n0, tid);
    issue_chunk(1, sb + STAGE_BYTES, a, b, row0, n0, tid);

    for (int i = 0; i < NC; ++i) {
        if (i < NC - 1) cp_wait<1>();
        else            cp_wait<0>();
        __syncthreads();                 // stage i ready; slot (i-1)%3 drained

        int j = i + 2;                   // prefetch into slot (i+2)%3
        if (j < NC) {
            uint32_t slot = (uint32_t)(j % 3) * STAGE_BYTES;
            issue_chunk(j, sb + slot, a, b, row0, n0, tid);
        }

        uint32_t st = sb + (uint32_t)(i % 3) * STAGE_BYTES;
        uint32_t bb = st + 16384u;
#pragma unroll
        for (int ks = 0; ks < 4; ++ks) {
            uint32_t bf[4][4];
#pragma unroll
            for (int bi = 0; bi < 4; ++bi) {
                int r = brow + bi * 16;
                uint32_t addr = bb + (uint32_t)(r * 128)
                              + ((uint32_t)((ks * 2 + bhl) ^ (r & 7)) << 4);
                ldsm4(bf[bi], addr);
            }
            uint32_t af[4][4];
#pragma unroll
            for (int mi = 0; mi < 4; ++mi) {
                int r = arow + mi * 16;
                uint32_t addr = st + (uint32_t)(r * 128)
                              + ((uint32_t)((ks * 2 + ahl) ^ (r & 7)) << 4);
                ldsm4(af[mi], addr);
            }
#pragma unroll
            for (int mi = 0; mi < 4; ++mi)
#pragma unroll
                for (int ni = 0; ni < 8; ++ni)
                    mma16816(acc[mi][ni], af[mi], &bf[ni >> 1][(ni & 1) * 2]);
        }
    }
}

// ---------------- GEMM1: h = tanh((v_p-0.5)@W1+b1) -> fp16 (reg epilogue) ---
__global__ __launch_bounds__(128, 2) void k_gemm1_tc(const float* __restrict__ b1)
{
    extern __shared__ char dsm[];
    const int tid  = threadIdx.x;
    const int wid  = tid >> 5;
    const int lane = tid & 31;
    const int wm   = wid >> 1, wn = wid & 1;
    const int l3   = lane & 3, gid = lane >> 2;
    const int row0 = blockIdx.y * 128;
    const int n0   = blockIdx.x * 128;

    float acc[4][8][4];
    gemm_mainloop(g_a1, g_w1, row0, n0, smem_u32(dsm), tid, lane, wm, wn, acc);

    float b1v[8][2];
#pragma unroll
    for (int ni = 0; ni < 8; ++ni) {
        int c = n0 + wn * 64 + ni * 8 + l3 * 2;
        b1v[ni][0] = b1[c]; b1v[ni][1] = b1[c + 1];
    }
#pragma unroll
    for (int mi = 0; mi < 4; ++mi) {
        int r = row0 + wm * 64 + mi * 16 + gid;
#pragma unroll
        for (int ni = 0; ni < 8; ++ni) {
            int cg = n0 + wn * 64 + ni * 8 + l3 * 2;
            float t0 = fast_tanh(acc[mi][ni][0] + b1v[ni][0]);
            float t1 = fast_tanh(acc[mi][ni][1] + b1v[ni][1]);
            float t2 = fast_tanh(acc[mi][ni][2] + b1v[ni][0]);
            float t3 = fast_tanh(acc[mi][ni][3] + b1v[ni][1]);
            *(__half2*)&g_h[(size_t)r * HDIM + cg]       = __floats2half2_rn(t0, t1);
            *(__half2*)&g_h[(size_t)(r + 8) * HDIM + cg] = __floats2half2_rn(t2, t3);
        }
    }
}

// ---------------- GEMM2 fused (register epilogue, quad-shuffle softmax) -----
__device__ __forceinline__ void epi_row(
    float a0, float a1, float a2, float a3, const float* bv,
    int j0, int j1, int j2, int j3,
    const float* __restrict__ v_in, int grow, int h, int l3,
    float* vbuf, float* redb, int r, int hl)
{
    float e0 = __expf(fast_tanh(a0 + bv[0]));
    float e1 = __expf(fast_tanh(a1 + bv[1]));
    float e2 = __expf(fast_tanh(a2 + bv[2]));
    float e3 = __expf(fast_tanh(a3 + bv[3]));
    float s = e0 + e1 + e2 + e3;
    float v = v_in[(size_t)grow * 1024 + 512 + h];
    int kk = (int)(v * 16.f); kk = kk < 0 ? 0 : (kk > 15 ? 15 : kk);
    float pref = (j0 < kk ? e0 : 0.f) + (j1 < kk ? e1 : 0.f)
               + (j2 < kk ? e2 : 0.f) + (j3 < kk ? e3 : 0.f);
    float pk = (j0 == kk) ? e0 : ((j1 == kk) ? e1 : ((j2 == kk) ? e2 : ((j3 == kk) ? e3 : 0.f)));
    s    += __shfl_xor_sync(0xffffffffu, s,    1);
    s    += __shfl_xor_sync(0xffffffffu, s,    2);
    pref += __shfl_xor_sync(0xffffffffu, pref, 1);
    pref += __shfl_xor_sync(0xffffffffu, pref, 2);
    pk   += __shfl_xor_sync(0xffffffffu, pk,   1);
    pk   += __shfl_xor_sync(0xffffffffu, pk,   2);
    if (l3 == 0) {
        float inv   = __fdividef(1.f, s);
        float p     = pk * inv;
        float y     = pref * inv;
        float alpha = v * 16.f - (float)kk;
        vbuf[r * 8 + hl] = y + alpha * p;
        redb[r * 8 + hl] = __logf(p);
    }
}

__global__ __launch_bounds__(128, 2) void k_gemm2_tc(
    const float* __restrict__ v_in, const float* __restrict__ b2,
    float* __restrict__ dout)
{
    extern __shared__ char dsm[];
    float* vbuf = (float*)(dsm + 3 * STAGE_BYTES);   // [128][8]
    float* redb = vbuf + 1024;                        // [128][8]
    const int tid  = threadIdx.x;
    const int wid  = tid >> 5;
    const int lane = tid & 31;
    const int wm   = wid >> 1, wn = wid & 1;
    const int l3   = lane & 3, gid = lane >> 2;
    const int row0 = blockIdx.y * 128;
    const int n0   = blockIdx.x * 128;
    const int hbase = n0 >> 4;

    float acc[4][8][4];
    gemm_mainloop(g_h, g_w2, row0, n0, smem_u32(dsm), tid, lane, wm, wn, acc);

    const int j0 = l3 * 2, j1 = j0 + 1, j2 = j0 + 8, j3 = j0 + 9;
    float b2v[4][4];
#pragma unroll
    for (int g = 0; g < 4; ++g) {
        int cb = n0 + wn * 64 + g * 16;
        b2v[g][0] = b2[cb + j0]; b2v[g][1] = b2[cb + j1];
        b2v[g][2] = b2[cb + j2]; b2v[g][3] = b2[cb + j3];
    }
#pragma unroll
    for (int mi = 0; mi < 4; ++mi) {
        int r = wm * 64 + mi * 16 + gid;
#pragma unroll
        for (int g = 0; g < 4; ++g) {
            int hl = wn * 4 + g;
            int h  = hbase + hl;
            epi_row(acc[mi][2*g][0], acc[mi][2*g][1], acc[mi][2*g+1][0], acc[mi][2*g+1][1],
                    b2v[g], j0, j1, j2, j3, v_in, row0 + r, h, l3, vbuf, redb, r, hl);
            epi_row(acc[mi][2*g][2], acc[mi][2*g][3], acc[mi][2*g+1][2], acc[mi][2*g+1][3],
                    b2v[g], j0, j1, j2, j3, v_in, row0 + r + 8, h, l3, vbuf, redb, r + 8, hl);
        }
    }
    __syncthreads();

    {   // v_out_active writes: one row (32B) per thread
        int r = tid;
        float4 w0 = *(float4*)&vbuf[r * 8];
        float4 w1 = *(float4*)&vbuf[r * 8 + 4];
        float* d = &dout[(size_t)(row0 + r) * 1024 + 512 + hbase];
        *(float4*)d = w0;
        *(float4*)(d + 4) = w1;
    }
    {   // per-row partial log-p, coalesced layout [ntile][row]
        float s = 0.f;
#pragma unroll
        for (int g = 0; g < 8; ++g) s += redb[tid * 8 + g];
        g_ldp[(size_t)blockIdx.x * BQ + row0 + tid] = s;
    }
}

// ---------------- merged prep + finalize ------------------------------------
__device__ __forceinline__ void prep_wt(
    const float* __restrict__ W, __half* th, int N, int bx, int by, int tid)
{
    __shared__ float t[32][33];
    int n0 = bx * 32, k0 = by * 32;
    int tx = tid & 31, ty = tid >> 5;
#pragma unroll
    for (int i = 0; i < 4; ++i)
        t[ty + 8 * i][tx] = W[(size_t)(k0 + ty + 8 * i) * N + n0 + tx];
    __syncthreads();
#pragma unroll
    for (int i = 0; i < 4; ++i)
        th[(size_t)(n0 + ty + 8 * i) * HDIM + k0 + tx] = __float2half_rn(t[tx][ty + 8 * i]);
}

__global__ __launch_bounds__(256) void k_prep(
    const float* __restrict__ v_in, const float* __restrict__ W1,
    const float* __restrict__ W2, float* __restrict__ out)
{
    int b = blockIdx.x, tid = threadIdx.x;
    if (b < 4096) {                       // a1 + passive copy
        int i = b * 256 + tid;            // float4 over [BQ,128]
        int row = i >> 7, c4 = i & 127;
        float4 v = ((const float4*)v_in)[(size_t)row * 256 + c4];
        ((float4*)out)[(size_t)row * 256 + c4] = v;
        __half2 h0 = __floats2half2_rn(v.x - 0.5f, v.y - 0.5f);
        __half2 h1 = __floats2half2_rn(v.z - 0.5f, v.w - 0.5f);
        __half2* ph = (__half2*)&g_a1[(size_t)row * HDIM + c4 * 4];
        ph[0] = h0; ph[1] = h1;
    } else if (b < 4352) {
        int bb = b - 4096;                // W1: 16 x 16
        prep_wt(W1, g_w1, HDIM, bb & 15, bb >> 4, tid);
    } else {
        int bb = b - 4352;                // W2: 256 x 16
        prep_wt(W2, g_w2, HK, bb & 255, bb >> 8, tid);
    }
}

__global__ __launch_bounds__(256) void k_finalize(const float* __restrict__ logd,
                                                  float* __restrict__ dout)
{
    int b = blockIdx.x * 256 + threadIdx.x;
    if (b < BQ) {
        float s = 0.f;
#pragma unroll
        for (int i = 0; i < NT2; ++i)       // coalesced: stride BQ columns
            s += g_ldp[(size_t)i * BQ + b];
        dout[(size_t)BQ * 1024 + b] = logd[b] - s;
    }
}

// ---------------- launch -----------------------------------------------------
extern "C" void kernel_launch(void* const* d_in, const int* in_sizes, int n_in,
                              void* d_out, int out_size)
{
    const float* v_in = (const float*)d_in[0];
    const float* logd = (const float*)d_in[1];
    const float* W1   = (const float*)d_in[2];
    const float* b1   = (const float*)d_in[3];
    const float* W2   = (const float*)d_in[4];
    const float* b2   = (const float*)d_in[5];
    float* out = (float*)d_out;

    cudaFuncSetAttribute(k_gemm1_tc, cudaFuncAttributeMaxDynamicSharedMemorySize, DYN1);
    cudaFuncSetAttribute(k_gemm2_tc, cudaFuncAttributeMaxDynamicSharedMemorySize, DYN2);

    k_prep<<<8448, 256>>>(v_in, W1, W2, out);
    k_gemm1_tc<<<dim3(4, 64),  128, DYN1>>>(b1);
    k_gemm2_tc<<<dim3(64, 64), 128, DYN2>>>(v_in, b2, out);
    k_finalize<<<32, 256>>>(logd, out);
}

// round 11
// speedup vs baseline: 1.0528x; 1.0528x over previous
#include <cuda_runtime.h>
#include <cuda_fp16.h>
#include <cstdint>

#define BQ 8192
#define HDIM 512
#define HK 8192
#define NT2 64               // gemm2 n-tiles = 8192/128
#define NTILES 4096          // 64 x 64 tiles for gemm2
#define NCTA 296             // persistent CTAs (2 x 148 SM)
#define NC 8                 // k chunks of 64
#define STAGE_BYTES 32768    // A 16K + B 16K
#define DYN1 98304           // gemm1: 3 stages
#define DYN2 106496          // gemm2: 3 stages + vbuf 4K + red 4K

// ---------------- device scratch (no cudaMalloc allowed) -------------------
__device__ __align__(16) __half g_a1[BQ*HDIM];
__device__ __align__(16) __half g_h [BQ*HDIM];
__device__ __align__(16) __half g_w1[HDIM*HDIM];
__device__ __align__(16) __half g_w2[(size_t)HK*HDIM];
__device__ float g_ldp[(size_t)NT2*BQ];   // [ntile][row] coalesced both sides

// ---------------- helpers ---------------------------------------------------
__device__ __forceinline__ uint32_t smem_u32(const void* p){
    uint32_t a;
    asm("{ .reg .u64 t; cvta.to.shared.u64 t, %1; cvt.u32.u64 %0, t; }" : "=r"(a) : "l"(p));
    return a;
}
__device__ __forceinline__ void cp16(uint32_t dst, const void* src){
    asm volatile("cp.async.cg.shared.global [%0], [%1], 16;" :: "r"(dst), "l"(src));
}
__device__ __forceinline__ void cp_commit(){
    asm volatile("cp.async.commit_group;" ::: "memory");
}
template<int N> __device__ __forceinline__ void cp_wait(){
    asm volatile("cp.async.wait_group %0;" :: "n"(N) : "memory");
}
__device__ __forceinline__ void ldsm4(uint32_t* r, uint32_t addr){
    asm volatile("ldmatrix.sync.aligned.m8n8.x4.shared.b16 {%0,%1,%2,%3}, [%4];"
        : "=r"(r[0]), "=r"(r[1]), "=r"(r[2]), "=r"(r[3]) : "r"(addr));
}
__device__ __forceinline__ void mma16816(float* d, const uint32_t* a, const uint32_t* b){
    asm volatile("mma.sync.aligned.m16n8k16.row.col.f32.f16.f16.f32 "
        "{%0,%1,%2,%3},{%4,%5,%6,%7},{%8,%9},{%0,%1,%2,%3};"
        : "+f"(d[0]), "+f"(d[1]), "+f"(d[2]), "+f"(d[3])
        : "r"(a[0]), "r"(a[1]), "r"(a[2]), "r"(a[3]), "r"(b[0]), "r"(b[1]));
}
__device__ __forceinline__ float fast_tanh(float x){
    x = fminf(fmaxf(x, -15.f), 15.f);
    float e = __expf(2.f * x);
    return __fdividef(e - 1.f, e + 1.f);
}

// ---------------- chunk issue (256 threads) ---------------------------------
__device__ __forceinline__ void issue_chunk(
    uint32_t sbase, const __half* __restrict__ a, const __half* __restrict__ b,
    int row0, int n0, int kk, int tid)
{
#pragma unroll
    for (int j = 0; j < 4; ++j) {                // A: 128 rows x 128B
        int i = tid + 256 * j;
        int r = i >> 3, q = i & 7;
        uint32_t sw = (uint32_t)(r * 128) + ((uint32_t)(q ^ (r & 7)) << 4);
        cp16(sbase + sw, a + (size_t)(row0 + r) * HDIM + kk + q * 8);
    }
#pragma unroll
    for (int j = 0; j < 4; ++j) {                // B: 128 n-rows x 128B
        int i = tid + 256 * j;
        int r = i >> 3, q = i & 7;
        uint32_t sw = (uint32_t)(r * 128) + ((uint32_t)(q ^ (r & 7)) << 4);
        cp16(sbase + 16384u + sw, b + (size_t)(n0 + r) * HDIM + kk + q * 8);
    }
    cp_commit();
}

// ---------------- GEMM1 (round-9 proven config) ------------------------------
__global__ __launch_bounds__(256, 2) void k_gemm1_tc(const float* __restrict__ b1)
{
    extern __shared__ char dsm[];
    const int tid  = threadIdx.x;
    const int wid  = tid >> 5;
    const int lane = tid & 31;
    const int wm   = wid & 1, wn = wid >> 1;
    const int l3   = lane & 3, gid = lane >> 2;
    const int row0 = blockIdx.y * 128;
    const int n0   = blockIdx.x * 128;
    const uint32_t sb = smem_u32(dsm);

    float acc[4][4][4];
#pragma unroll
    for (int mi = 0; mi < 4; ++mi)
#pragma unroll
        for (int ni = 0; ni < 4; ++ni)
#pragma unroll
            for (int q = 0; q < 4; ++q) acc[mi][ni][q] = 0.f;

    const int arow = wm * 64 + (lane & 15);
    const int ahl  = lane >> 4;
    const int brow = wn * 32 + (lane & 7) + ((lane >> 4) << 3);
    const int bhl  = (lane >> 3) & 1;

    issue_chunk(sb,               g_a1, g_w1, row0, n0, 0,  tid);
    issue_chunk(sb + STAGE_BYTES, g_a1, g_w1, row0, n0, 64, tid);

    for (int i = 0; i < NC; ++i) {
        if (i < NC - 1) cp_wait<1>();
        else            cp_wait<0>();
        __syncthreads();
        int j = i + 2;
        if (j < NC)
            issue_chunk(sb + (uint32_t)(j % 3) * STAGE_BYTES, g_a1, g_w1,
                        row0, n0, j << 6, tid);

        uint32_t st = sb + (uint32_t)(i % 3) * STAGE_BYTES;
        uint32_t bb = st + 16384u;
#pragma unroll
        for (int ks = 0; ks < 4; ++ks) {
            uint32_t bf[2][4];
#pragma unroll
            for (int bi = 0; bi < 2; ++bi) {
                int r = brow + bi * 16;
                uint32_t addr = bb + (uint32_t)(r * 128)
                              + ((uint32_t)((ks * 2 + bhl) ^ (r & 7)) << 4);
                ldsm4(bf[bi], addr);
            }
            uint32_t af[4][4];
#pragma unroll
            for (int mi = 0; mi < 4; ++mi) {
                int r = arow + mi * 16;
                uint32_t addr = st + (uint32_t)(r * 128)
                              + ((uint32_t)((ks * 2 + ahl) ^ (r & 7)) << 4);
                ldsm4(af[mi], addr);
            }
#pragma unroll
            for (int mi = 0; mi < 4; ++mi)
#pragma unroll
                for (int ni = 0; ni < 4; ++ni)
                    mma16816(acc[mi][ni], af[mi], &bf[ni >> 1][(ni & 1) * 2]);
        }
    }

    float b1v[4][2];
#pragma unroll
    for (int ni = 0; ni < 4; ++ni) {
        int c = n0 + wn * 32 + ni * 8 + l3 * 2;
        b1v[ni][0] = b1[c]; b1v[ni][1] = b1[c + 1];
    }
#pragma unroll
    for (int mi = 0; mi < 4; ++mi) {
        int r = row0 + wm * 64 + mi * 16 + gid;
#pragma unroll
        for (int ni = 0; ni < 4; ++ni) {
            int cg = n0 + wn * 32 + ni * 8 + l3 * 2;
            float t0 = fast_tanh(acc[mi][ni][0] + b1v[ni][0]);
            float t1 = fast_tanh(acc[mi][ni][1] + b1v[ni][1]);
            float t2 = fast_tanh(acc[mi][ni][2] + b1v[ni][0]);
            float t3 = fast_tanh(acc[mi][ni][3] + b1v[ni][1]);
            *(__half2*)&g_h[(size_t)r * HDIM + cg]       = __floats2half2_rn(t0, t1);
            *(__half2*)&g_h[(size_t)(r + 8) * HDIM + cg] = __floats2half2_rn(t2, t3);
        }
    }
}

// ---------------- GEMM2 epilogue helper --------------------------------------
__device__ __forceinline__ void epi_row(
    float a0, float a1, float a2, float a3, const float* bv,
    int j0, int j1, int j2, int j3,
    const float* __restrict__ v_in, int grow, int h, int l3,
    float* vbuf, float* redb, int r, int hl)
{
    float e0 = __expf(fast_tanh(a0 + bv[0]));
    float e1 = __expf(fast_tanh(a1 + bv[1]));
    float e2 = __expf(fast_tanh(a2 + bv[2]));
    float e3 = __expf(fast_tanh(a3 + bv[3]));
    float s = e0 + e1 + e2 + e3;
    float v = v_in[(size_t)grow * 1024 + 512 + h];
    int kk = (int)(v * 16.f); kk = kk < 0 ? 0 : (kk > 15 ? 15 : kk);
    float pref = (j0 < kk ? e0 : 0.f) + (j1 < kk ? e1 : 0.f)
               + (j2 < kk ? e2 : 0.f) + (j3 < kk ? e3 : 0.f);
    float pk = (j0 == kk) ? e0 : ((j1 == kk) ? e1 : ((j2 == kk) ? e2 : ((j3 == kk) ? e3 : 0.f)));
    s    += __shfl_xor_sync(0xffffffffu, s,    1);
    s    += __shfl_xor_sync(0xffffffffu, s,    2);
    pref += __shfl_xor_sync(0xffffffffu, pref, 1);
    pref += __shfl_xor_sync(0xffffffffu, pref, 2);
    pk   += __shfl_xor_sync(0xffffffffu, pk,   1);
    pk   += __shfl_xor_sync(0xffffffffu, pk,   2);
    if (l3 == 0) {
        float inv   = __fdividef(1.f, s);
        float p     = pk * inv;
        float y     = pref * inv;
        float alpha = v * 16.f - (float)kk;
        vbuf[r * 8 + hl] = y + alpha * p;
        redb[r * 8 + hl] = __logf(p);
    }
}

// ---------------- GEMM2: persistent, flat cross-tile chunk stream ------------
__global__ __launch_bounds__(256, 2) void k_gemm2_tc(
    const float* __restrict__ v_in, const float* __restrict__ b2,
    float* __restrict__ dout)
{
    extern __shared__ char dsm[];
    float* vbuf = (float*)(dsm + 3 * STAGE_BYTES);   // [128][8]
    float* redb = vbuf + 1024;                        // [128][8]
    const int tid  = threadIdx.x;
    const int wid  = tid >> 5;
    const int lane = tid & 31;
    const int wm   = wid & 1, wn = wid >> 1;
    const int l3   = lane & 3, gid = lane >> 2;
    const uint32_t sb = smem_u32(dsm);

    const int c0  = blockIdx.x;
    // 4096 = 248*14 + 48*13
    const int ntl  = (c0 < 248) ? 14 : 13;
    const int ftot = ntl * NC;

    const int arow = wm * 64 + (lane & 15);
    const int ahl  = lane >> 4;
    const int brow = wn * 32 + (lane & 7) + ((lane >> 4) << 3);
    const int bhl  = (lane >> 3) & 1;
    const int j0 = l3 * 2, j1 = j0 + 1, j2 = j0 + 8, j3 = j0 + 9;

    // flat-chunk issue: f -> (tile j, chunk c)
    auto issue_f = [&](int f){
        int jt = f >> 3;
        int t  = c0 + jt * NCTA;
        int n0i   = (t & 63) << 7;
        int row0i = (t >> 6) << 7;
        issue_chunk(sb + (uint32_t)(f % 3) * STAGE_BYTES,
                    g_h, g_w2, row0i, n0i, (f & 7) << 6, tid);
    };

    issue_f(0);
    issue_f(1);

    for (int jt = 0; jt < ntl; ++jt) {
        const int t     = c0 + jt * NCTA;
        const int n0    = (t & 63) << 7;
        const int row0  = (t >> 6) << 7;
        const int ntile = t & 63;
        const int hbase = n0 >> 4;

        float acc[4][4][4];
#pragma unroll
        for (int mi = 0; mi < 4; ++mi)
#pragma unroll
            for (int ni = 0; ni < 4; ++ni)
#pragma unroll
                for (int q = 0; q < 4; ++q) acc[mi][ni][q] = 0.f;

        for (int i = 0; i < NC; ++i) {
            int f = jt * NC + i;
            if (f == ftot - 1) cp_wait<0>();
            else               cp_wait<1>();
            __syncthreads();               // chunk f ready; slot (f+2)%3 drained
            if (f + 2 < ftot) issue_f(f + 2);

            uint32_t st = sb + (uint32_t)(f % 3) * STAGE_BYTES;
            uint32_t bb = st + 16384u;
#pragma unroll
            for (int ks = 0; ks < 4; ++ks) {
                uint32_t bf[2][4];
#pragma unroll
                for (int bi = 0; bi < 2; ++bi) {
                    int r = brow + bi * 16;
                    uint32_t addr = bb + (uint32_t)(r * 128)
                                  + ((uint32_t)((ks * 2 + bhl) ^ (r & 7)) << 4);
                    ldsm4(bf[bi], addr);
                }
                uint32_t af[4][4];
#pragma unroll
                for (int mi = 0; mi < 4; ++mi) {
                    int r = arow + mi * 16;
                    uint32_t addr = st + (uint32_t)(r * 128)
                                  + ((uint32_t)((ks * 2 + ahl) ^ (r & 7)) << 4);
                    ldsm4(af[mi], addr);
                }
#pragma unroll
                for (int mi = 0; mi < 4; ++mi)
#pragma unroll
                    for (int ni = 0; ni < 4; ++ni)
                        mma16816(acc[mi][ni], af[mi], &bf[ni >> 1][(ni & 1) * 2]);
            }
        }

        // epilogue for tile t (next tile's first chunks already in flight)
        float b2v[2][4];
#pragma unroll
        for (int g = 0; g < 2; ++g) {
            int cb = n0 + wn * 32 + g * 16;
            b2v[g][0] = b2[cb + j0]; b2v[g][1] = b2[cb + j1];
            b2v[g][2] = b2[cb + j2]; b2v[g][3] = b2[cb + j3];
        }
#pragma unroll
        for (int mi = 0; mi < 4; ++mi) {
            int r = wm * 64 + mi * 16 + gid;
#pragma unroll
            for (int g = 0; g < 2; ++g) {
                int hl = wn * 2 + g;
                int h  = hbase + hl;
                epi_row(acc[mi][2*g][0], acc[mi][2*g][1], acc[mi][2*g+1][0], acc[mi][2*g+1][1],
                        b2v[g], j0, j1, j2, j3, v_in, row0 + r, h, l3, vbuf, redb, r, hl);
                epi_row(acc[mi][2*g][2], acc[mi][2*g][3], acc[mi][2*g+1][2], acc[mi][2*g+1][3],
                        b2v[g], j0, j1, j2, j3, v_in, row0 + r + 8, h, l3, vbuf, redb, r + 8, hl);
            }
        }
        __syncthreads();

        {   // coalesced v_out_active writes
            int r = tid >> 1, cc = (tid & 1) * 4;
            float4 w = *(float4*)&vbuf[r * 8 + cc];
            *(float4*)&dout[(size_t)(row0 + r) * 1024 + 512 + hbase + cc] = w;
        }
        if (tid < 128) {
            float s = 0.f;
#pragma unroll
            for (int g = 0; g < 8; ++g) s += redb[tid * 8 + g];
            g_ldp[(size_t)ntile * BQ + row0 + tid] = s;
        }
        // vbuf/redb reuse next tile is protected by the 8 per-chunk barriers
    }
}

// ---------------- merged prep + finalize ------------------------------------
__device__ __forceinline__ void prep_wt(
    const float* __restrict__ W, __half* th, int N, int bx, int by, int tid)
{
    __shared__ float t[32][33];
    int n0 = bx * 32, k0 = by * 32;
    int tx = tid & 31, ty = tid >> 5;
#pragma unroll
    for (int i = 0; i < 4; ++i)
        t[ty + 8 * i][tx] = W[(size_t)(k0 + ty + 8 * i) * N + n0 + tx];
    __syncthreads();
#pragma unroll
    for (int i = 0; i < 4; ++i)
        th[(size_t)(n0 + ty + 8 * i) * HDIM + k0 + tx] = __float2half_rn(t[tx][ty + 8 * i]);
}

__global__ __launch_bounds__(256) void k_prep(
    const float* __restrict__ v_in, const float* __restrict__ W1,
    const float* __restrict__ W2, float* __restrict__ out)
{
    int b = blockIdx.x, tid = threadIdx.x;
    if (b < 4096) {                       // a1 + passive copy
        int i = b * 256 + tid;            // float4 over [BQ,128]
        int row = i >> 7, c4 = i & 127;
        float4 v = ((const float4*)v_in)[(size_t)row * 256 + c4];
        ((float4*)out)[(size_t)row * 256 + c4] = v;
        __half2 h0 = __floats2half2_rn(v.x - 0.5f, v.y - 0.5f);
        __half2 h1 = __floats2half2_rn(v.z - 0.5f, v.w - 0.5f);
        __half2* ph = (__half2*)&g_a1[(size_t)row * HDIM + c4 * 4];
        ph[0] = h0; ph[1] = h1;
    } else if (b < 4352) {
        int bb = b - 4096;                // W1: 16 x 16
        prep_wt(W1, g_w1, HDIM, bb & 15, bb >> 4, tid);
    } else {
        int bb = b - 4352;                // W2: 256 x 16
        prep_wt(W2, g_w2, HK, bb & 255, bb >> 8, tid);
    }
}

__global__ __launch_bounds__(256) void k_finalize(const float* __restrict__ logd,
                                                  float* __restrict__ dout)
{
    int b = blockIdx.x * 256 + threadIdx.x;
    if (b < BQ) {
        float s = 0.f;
#pragma unroll
        for (int i = 0; i < NT2; ++i)       // coalesced: stride BQ columns
            s += g_ldp[(size_t)i * BQ + b];
        dout[(size_t)BQ * 1024 + b] = logd[b] - s;
    }
}

// ---------------- launch -----------------------------------------------------
extern "C" void kernel_launch(void* const* d_in, const int* in_sizes, int n_in,
                              void* d_out, int out_size)
{
    const float* v_in = (const float*)d_in[0];
    const float* logd = (const float*)d_in[1];
    const float* W1   = (const float*)d_in[2];
    const float* b1   = (const float*)d_in[3];
    const float* W2   = (const float*)d_in[4];
    const float* b2   = (const float*)d_in[5];
    float* out = (float*)d_out;

    cudaFuncSetAttribute(k_gemm1_tc, cudaFuncAttributeMaxDynamicSharedMemorySize, DYN1);
    cudaFuncSetAttribute(k_gemm2_tc, cudaFuncAttributeMaxDynamicSharedMemorySize, DYN2);

    k_prep<<<8448, 256>>>(v_in, W1, W2, out);
    k_gemm1_tc<<<dim3(4, 64), 256, DYN1>>>(b1);
    k_gemm2_tc<<<NCTA, 256, DYN2>>>(v_in, b2, out);
    k_finalize<<<32, 256>>>(logd, out);
}